// round 2
// baseline (speedup 1.0000x reference)
#include <cuda_runtime.h>

#define NN 50000
#define EE 1600000
#define KHOPS 16

// ---- device scratch (no allocations allowed) ----
__device__ int    g_deg[NN];
__device__ int    g_rowptr[NN + 1];
__device__ int    g_cursor[NN];
__device__ int    g_col[EE];
__device__ int2   g_cw[EE];          // packed {src, weight-as-int}
__device__ float  g_dinv[NN];
__device__ float4 g_xa[NN * 32];
__device__ float4 g_xb[NN * 32];
__device__ float4 g_h[NN * 32];

__global__ void k_zero_deg() {
    int i = blockIdx.x * blockDim.x + threadIdx.x;
    if (i < NN) g_deg[i] = 0;
}

__global__ void k_degree(const int* __restrict__ dst) {
    int e = blockIdx.x * blockDim.x + threadIdx.x;
    if (e < EE) atomicAdd(&g_deg[dst[e]], 1);
}

__global__ void k_dinv() {
    int i = blockIdx.x * blockDim.x + threadIdx.x;
    if (i < NN) g_dinv[i] = rsqrtf((float)(g_deg[i] + 1));  // +1 self loop
}

// single-block exclusive scan of g_deg -> g_rowptr
__global__ void k_scan() {
    __shared__ int tmp[1024];
    __shared__ int carry_s;
    int t = threadIdx.x;
    if (t == 0) carry_s = 0;
    __syncthreads();
    for (int base = 0; base < NN; base += 1024) {
        int i = base + t;
        int v = (i < NN) ? g_deg[i] : 0;
        tmp[t] = v;
        __syncthreads();
        for (int off = 1; off < 1024; off <<= 1) {
            int add = (t >= off) ? tmp[t - off] : 0;
            __syncthreads();
            tmp[t] += add;
            __syncthreads();
        }
        int incl  = tmp[t];
        int total = tmp[1023];
        int carry = carry_s;
        if (i < NN) g_rowptr[i] = carry + incl - v;
        __syncthreads();
        if (t == 0) carry_s = carry + total;
        __syncthreads();
    }
    if (t == 0) g_rowptr[NN] = carry_s;
}

__global__ void k_cursor() {
    int i = blockIdx.x * blockDim.x + threadIdx.x;
    if (i < NN) g_cursor[i] = g_rowptr[i];
}

__global__ void k_fill(const int* __restrict__ src, const int* __restrict__ dst) {
    int e = blockIdx.x * blockDim.x + threadIdx.x;
    if (e < EE) {
        int d = dst[e];
        int p = atomicAdd(&g_cursor[d], 1);
        g_col[p] = src[e];
    }
}

// deterministic order: per-row insertion sort by src value, then pack {src, w}
__global__ void k_sort_w() {
    int r = blockIdx.x * blockDim.x + threadIdx.x;
    if (r >= NN) return;
    int beg = g_rowptr[r], end = g_rowptr[r + 1];
    for (int i = beg + 1; i < end; i++) {
        int key = g_col[i];
        int j = i - 1;
        while (j >= beg && g_col[j] > key) { g_col[j + 1] = g_col[j]; j--; }
        g_col[j + 1] = key;
    }
    float dr = g_dinv[r];
    for (int p = beg; p < end; p++) {
        int s = g_col[p];
        float w = dr * g_dinv[s];
        g_cw[p] = make_int2(s, __float_as_int(w));
    }
}

__global__ void k_init_h(const float4* __restrict__ x0) {
    int i = blockIdx.x * blockDim.x + threadIdx.x;
    if (i < NN * 32) {
        float4 v = x0[i];
        g_h[i] = make_float4(0.05f * v.x, 0.05f * v.y, 0.05f * v.z, 0.05f * v.w);
    }
}

// one warp per node; lane = one float4 slice of the 128-wide row
__global__ void __launch_bounds__(256) k_hop(const float4* __restrict__ x0, int k) {
    int gw   = (blockIdx.x * blockDim.x + threadIdx.x) >> 5;
    int lane = threadIdx.x & 31;
    if (gw >= NN) return;
    const float4* xin = (k == 0) ? x0 : ((k & 1) ? g_xa : g_xb);
    float4* xout = (k & 1) ? g_xb : g_xa;

    int   base = gw * 32 + lane;
    float di   = g_dinv[gw];
    float s2   = di * di;
    float4 xi  = xin[base];
    float4 acc = make_float4(s2 * xi.x, s2 * xi.y, s2 * xi.z, s2 * xi.w);

    int j   = g_rowptr[gw];
    int end = g_rowptr[gw + 1];
    for (; j + 4 <= end; j += 4) {
        int2 c0 = g_cw[j], c1 = g_cw[j + 1], c2 = g_cw[j + 2], c3 = g_cw[j + 3];
        float4 v0 = xin[c0.x * 32 + lane];
        float4 v1 = xin[c1.x * 32 + lane];
        float4 v2 = xin[c2.x * 32 + lane];
        float4 v3 = xin[c3.x * 32 + lane];
        float w0 = __int_as_float(c0.y), w1 = __int_as_float(c1.y);
        float w2 = __int_as_float(c2.y), w3 = __int_as_float(c3.y);
        acc.x = fmaf(w0, v0.x, acc.x); acc.y = fmaf(w0, v0.y, acc.y);
        acc.z = fmaf(w0, v0.z, acc.z); acc.w = fmaf(w0, v0.w, acc.w);
        acc.x = fmaf(w1, v1.x, acc.x); acc.y = fmaf(w1, v1.y, acc.y);
        acc.z = fmaf(w1, v1.z, acc.z); acc.w = fmaf(w1, v1.w, acc.w);
        acc.x = fmaf(w2, v2.x, acc.x); acc.y = fmaf(w2, v2.y, acc.y);
        acc.z = fmaf(w2, v2.z, acc.z); acc.w = fmaf(w2, v2.w, acc.w);
        acc.x = fmaf(w3, v3.x, acc.x); acc.y = fmaf(w3, v3.y, acc.y);
        acc.z = fmaf(w3, v3.z, acc.z); acc.w = fmaf(w3, v3.w, acc.w);
    }
    for (; j < end; j++) {
        int2 c  = g_cw[j];
        float4 v = xin[c.x * 32 + lane];
        float  w = __int_as_float(c.y);
        acc.x = fmaf(w, v.x, acc.x); acc.y = fmaf(w, v.y, acc.y);
        acc.z = fmaf(w, v.z, acc.z); acc.w = fmaf(w, v.w, acc.w);
    }
    xout[base] = acc;

    const float cf = 0.95f / 16.0f;
    float4 hv = g_h[base];
    hv.x = fmaf(cf, acc.x, hv.x); hv.y = fmaf(cf, acc.y, hv.y);
    hv.z = fmaf(cf, acc.z, hv.z); hv.w = fmaf(cf, acc.w, hv.w);
    g_h[base] = hv;
}

// C[m, o] = sum_d h[m, d] * W[o, d] + bias[o].  64-row tile, full 128 cols.
__global__ void __launch_bounds__(256) k_gemm(const float* __restrict__ Wt,
                                              const float* __restrict__ bias,
                                              float* __restrict__ out) {
    __shared__ float Hs[64][33];
    __shared__ float Ws[128][34];
    int tid = threadIdx.x;
    int tx  = tid & 15;   // cols tx*8 .. tx*8+7
    int ty  = tid >> 4;   // rows ty*4 .. ty*4+3
    int row0 = blockIdx.x * 64;

    float acc[4][8];
#pragma unroll
    for (int r = 0; r < 4; r++)
#pragma unroll
        for (int o = 0; o < 8; o++) acc[r][o] = 0.f;

    const float4* w4 = (const float4*)Wt;
    for (int kc = 0; kc < 4; kc++) {
#pragma unroll
        for (int q = 0; q < 2; q++) {
            int idx = tid * 2 + q;           // 0..511
            int r = idx >> 3, c4 = idx & 7;
            int gr = row0 + r;
            float4 v = make_float4(0.f, 0.f, 0.f, 0.f);
            if (gr < NN) v = g_h[gr * 32 + kc * 8 + c4];
            Hs[r][c4 * 4 + 0] = v.x; Hs[r][c4 * 4 + 1] = v.y;
            Hs[r][c4 * 4 + 2] = v.z; Hs[r][c4 * 4 + 3] = v.w;
        }
#pragma unroll
        for (int q = 0; q < 4; q++) {
            int idx = tid * 4 + q;           // 0..1023
            int o = idx >> 3, c4 = idx & 7;
            float4 v = w4[o * 32 + kc * 8 + c4];
            Ws[o][c4 * 4 + 0] = v.x; Ws[o][c4 * 4 + 1] = v.y;
            Ws[o][c4 * 4 + 2] = v.z; Ws[o][c4 * 4 + 3] = v.w;
        }
        __syncthreads();
#pragma unroll
        for (int kk = 0; kk < 32; kk++) {
            float hreg[4], wreg[8];
#pragma unroll
            for (int r = 0; r < 4; r++) hreg[r] = Hs[ty * 4 + r][kk];
#pragma unroll
            for (int o = 0; o < 8; o++) wreg[o] = Ws[tx * 8 + o][kk];
#pragma unroll
            for (int r = 0; r < 4; r++)
#pragma unroll
                for (int o = 0; o < 8; o++)
                    acc[r][o] = fmaf(hreg[r], wreg[o], acc[r][o]);
        }
        __syncthreads();
    }

    float b[8];
#pragma unroll
    for (int o = 0; o < 8; o++) b[o] = bias[tx * 8 + o];
    float4* out4 = (float4*)out;
#pragma unroll
    for (int r = 0; r < 4; r++) {
        int gr = row0 + ty * 4 + r;
        if (gr < NN) {
            float4 lo = make_float4(acc[r][0] + b[0], acc[r][1] + b[1],
                                    acc[r][2] + b[2], acc[r][3] + b[3]);
            float4 hi = make_float4(acc[r][4] + b[4], acc[r][5] + b[5],
                                    acc[r][6] + b[6], acc[r][7] + b[7]);
            out4[gr * 32 + tx * 2 + 0] = lo;
            out4[gr * 32 + tx * 2 + 1] = hi;
        }
    }
}

extern "C" void kernel_launch(void* const* d_in, const int* in_sizes, int n_in,
                              void* d_out, int out_size) {
    const float* x0   = (const float*)d_in[0];
    const int*   ei   = (const int*)d_in[1];
    const float* Wt   = (const float*)d_in[2];
    const float* bias = (const float*)d_in[3];
    float*       out  = (float*)d_out;
    const int* src = ei;
    const int* dst = ei + EE;

    k_zero_deg<<<(NN + 255) / 256, 256>>>();
    k_degree<<<(EE + 255) / 256, 256>>>(dst);
    k_dinv<<<(NN + 255) / 256, 256>>>();
    k_scan<<<1, 1024>>>();
    k_cursor<<<(NN + 255) / 256, 256>>>();
    k_fill<<<(EE + 255) / 256, 256>>>(src, dst);
    k_sort_w<<<(NN + 127) / 128, 128>>>();
    k_init_h<<<(NN * 32 + 255) / 256, 256>>>((const float4*)x0);

    for (int k = 0; k < KHOPS; k++)
        k_hop<<<(NN * 32 + 255) / 256, 256>>>((const float4*)x0, k);

    k_gemm<<<(NN + 63) / 64, 256>>>(Wt, bias, out);
}

// round 5
// speedup vs baseline: 1.2914x; 1.2914x over previous
#include <cuda_runtime.h>
#include <cuda_fp16.h>

#define NN 50000
#define EE 1600000
#define KHOPS 16
#define NBLK ((NN + 1023) / 1024)

// ---- device scratch (no allocations allowed) ----
__device__ int    g_deg[NN];
__device__ int    g_rowptr[NN + 1];
__device__ int    g_cursor[NN];
__device__ int    g_col[EE];
__device__ int2   g_cw[EE];             // packed {src, weight-as-int}
__device__ float  g_dinv[NN];
__device__ int    g_bsum[NBLK];
__device__ __half g_x[KHOPS + 1][NN * 128];   // propagated states, fp16
__device__ float4 g_h[NN * 32];

__global__ void k_zero_deg() {
    int i = blockIdx.x * blockDim.x + threadIdx.x;
    if (i < NN) g_deg[i] = 0;
}

__global__ void k_degree(const int* __restrict__ dst) {
    int e = blockIdx.x * blockDim.x + threadIdx.x;
    if (e < EE) atomicAdd(&g_deg[dst[e]], 1);
}

__global__ void k_dinv() {
    int i = blockIdx.x * blockDim.x + threadIdx.x;
    if (i < NN) g_dinv[i] = rsqrtf((float)(g_deg[i] + 1));  // +1 self loop
}

// ---- 3-phase parallel exclusive scan of g_deg -> g_rowptr ----
__global__ void k_scan1() {
    __shared__ int tmp[1024];
    int t = threadIdx.x;
    int i = blockIdx.x * 1024 + t;
    int v = (i < NN) ? g_deg[i] : 0;
    tmp[t] = v;
    __syncthreads();
#pragma unroll
    for (int off = 1; off < 1024; off <<= 1) {
        int add = (t >= off) ? tmp[t - off] : 0;
        __syncthreads();
        tmp[t] += add;
        __syncthreads();
    }
    if (i < NN) g_rowptr[i] = tmp[t] - v;      // block-local exclusive
    if (t == 1023) g_bsum[blockIdx.x] = tmp[t];
}

__global__ void k_scan2() {
    if (threadIdx.x == 0) {
        int acc = 0;
        for (int b = 0; b < NBLK; b++) { int v = g_bsum[b]; g_bsum[b] = acc; acc += v; }
        g_rowptr[NN] = acc;
    }
}

__global__ void k_scan3() {
    int i = blockIdx.x * 1024 + threadIdx.x;
    if (i < NN) {
        int r = g_rowptr[i] + g_bsum[blockIdx.x];
        g_rowptr[i] = r;
        g_cursor[i] = r;
    }
}

__global__ void k_fill(const int* __restrict__ src, const int* __restrict__ dst) {
    int e = blockIdx.x * blockDim.x + threadIdx.x;
    if (e < EE) {
        int d = dst[e];
        int p = atomicAdd(&g_cursor[d], 1);
        g_col[p] = src[e];
    }
}

// deterministic order: per-row insertion sort by src value, then pack {src, w}
__global__ void k_sort_w() {
    int r = blockIdx.x * blockDim.x + threadIdx.x;
    if (r >= NN) return;
    int beg = g_rowptr[r], end = g_rowptr[r + 1];
    for (int i = beg + 1; i < end; i++) {
        int key = g_col[i];
        int j = i - 1;
        while (j >= beg && g_col[j] > key) { g_col[j + 1] = g_col[j]; j--; }
        g_col[j + 1] = key;
    }
    float dr = g_dinv[r];
    for (int p = beg; p < end; p++) {
        int s = g_col[p];
        float w = dr * g_dinv[s];
        g_cw[p] = make_int2(s, __float_as_int(w));
    }
}

// convert x0 fp32 -> g_x[0] fp16
__global__ void k_init(const float4* __restrict__ x0) {
    int i = blockIdx.x * blockDim.x + threadIdx.x;
    if (i < NN * 32) {
        float4 v = x0[i];
        uint2 u;
        __half2 lo = __floats2half2_rn(v.x, v.y);
        __half2 hi = __floats2half2_rn(v.z, v.w);
        u.x = *reinterpret_cast<unsigned*>(&lo);
        u.y = *reinterpret_cast<unsigned*>(&hi);
        ((uint2*)g_x[0])[i] = u;
    }
}

__device__ __forceinline__ void acc4(float& ax, float& ay, float& az, float& aw,
                                     float w, uint2 u) {
    __half2 h0 = *reinterpret_cast<__half2*>(&u.x);
    __half2 h1 = *reinterpret_cast<__half2*>(&u.y);
    float2 f0 = __half22float2(h0);
    float2 f1 = __half22float2(h1);
    ax = fmaf(w, f0.x, ax); ay = fmaf(w, f0.y, ay);
    az = fmaf(w, f1.x, az); aw = fmaf(w, f1.y, aw);
}

// one warp per node; lane covers 4 columns (8 bytes fp16) of the 128-wide row
__global__ void __launch_bounds__(256) k_hop(int k) {
    int gw   = (blockIdx.x * blockDim.x + threadIdx.x) >> 5;
    int lane = threadIdx.x & 31;
    if (gw >= NN) return;
    const __half* xin = g_x[k - 1];
    __half*       xout = g_x[k];

    float di = g_dinv[gw];
    float s2 = di * di;
    float ax = 0.f, ay = 0.f, az = 0.f, aw = 0.f;
    // self-loop term
    acc4(ax, ay, az, aw, s2, ((const uint2*)(xin + (size_t)gw * 128))[lane]);

    int j   = g_rowptr[gw];
    int end = g_rowptr[gw + 1];
    for (; j + 4 <= end; j += 4) {
        int2 c0 = g_cw[j], c1 = g_cw[j + 1], c2 = g_cw[j + 2], c3 = g_cw[j + 3];
        uint2 v0 = ((const uint2*)(xin + (size_t)c0.x * 128))[lane];
        uint2 v1 = ((const uint2*)(xin + (size_t)c1.x * 128))[lane];
        uint2 v2 = ((const uint2*)(xin + (size_t)c2.x * 128))[lane];
        uint2 v3 = ((const uint2*)(xin + (size_t)c3.x * 128))[lane];
        acc4(ax, ay, az, aw, __int_as_float(c0.y), v0);
        acc4(ax, ay, az, aw, __int_as_float(c1.y), v1);
        acc4(ax, ay, az, aw, __int_as_float(c2.y), v2);
        acc4(ax, ay, az, aw, __int_as_float(c3.y), v3);
    }
    for (; j < end; j++) {
        int2 c = g_cw[j];
        uint2 v = ((const uint2*)(xin + (size_t)c.x * 128))[lane];
        acc4(ax, ay, az, aw, __int_as_float(c.y), v);
    }

    uint2 o;
    __half2 lo = __floats2half2_rn(ax, ay);
    __half2 hi = __floats2half2_rn(az, aw);
    o.x = *reinterpret_cast<unsigned*>(&lo);
    o.y = *reinterpret_cast<unsigned*>(&hi);
    ((uint2*)(xout + (size_t)gw * 128))[lane] = o;
}

// h = alpha*x0 + (1-alpha)/K * sum_k x_k   (fp32 accumulate from fp16 buffers)
__global__ void k_finalize(const float4* __restrict__ x0) {
    int i = blockIdx.x * blockDim.x + threadIdx.x;
    if (i >= NN * 32) return;
    float4 v = x0[i];
    float sx = 0.f, sy = 0.f, sz = 0.f, sw = 0.f;
#pragma unroll
    for (int k = 1; k <= KHOPS; k++) {
        uint2 u = ((const uint2*)g_x[k])[i];
        __half2 h0 = *reinterpret_cast<__half2*>(&u.x);
        __half2 h1 = *reinterpret_cast<__half2*>(&u.y);
        float2 f0 = __half22float2(h0);
        float2 f1 = __half22float2(h1);
        sx += f0.x; sy += f0.y; sz += f1.x; sw += f1.y;
    }
    const float cf = 0.95f / 16.0f;
    g_h[i] = make_float4(fmaf(cf, sx, 0.05f * v.x), fmaf(cf, sy, 0.05f * v.y),
                         fmaf(cf, sz, 0.05f * v.z), fmaf(cf, sw, 0.05f * v.w));
}

// C[m, o] = sum_d h[m, d] * W[o, d] + bias[o].  64-row tile, full 128 cols.
__global__ void __launch_bounds__(256) k_gemm(const float* __restrict__ Wt,
                                              const float* __restrict__ bias,
                                              float* __restrict__ out) {
    __shared__ float Hs[64][33];
    __shared__ float Ws[128][34];
    int tid = threadIdx.x;
    int tx  = tid & 15;   // cols tx*8 .. tx*8+7
    int ty  = tid >> 4;   // rows ty*4 .. ty*4+3
    int row0 = blockIdx.x * 64;

    float acc[4][8];
#pragma unroll
    for (int r = 0; r < 4; r++)
#pragma unroll
        for (int o = 0; o < 8; o++) acc[r][o] = 0.f;

    const float4* w4 = (const float4*)Wt;
    for (int kc = 0; kc < 4; kc++) {
#pragma unroll
        for (int q = 0; q < 2; q++) {
            int idx = tid * 2 + q;           // 0..511
            int r = idx >> 3, c4 = idx & 7;
            int gr = row0 + r;
            float4 v = make_float4(0.f, 0.f, 0.f, 0.f);
            if (gr < NN) v = g_h[gr * 32 + kc * 8 + c4];
            Hs[r][c4 * 4 + 0] = v.x; Hs[r][c4 * 4 + 1] = v.y;
            Hs[r][c4 * 4 + 2] = v.z; Hs[r][c4 * 4 + 3] = v.w;
        }
#pragma unroll
        for (int q = 0; q < 4; q++) {
            int idx = tid * 4 + q;           // 0..1023
            int o = idx >> 3, c4 = idx & 7;
            float4 v = w4[o * 32 + kc * 8 + c4];
            Ws[o][c4 * 4 + 0] = v.x; Ws[o][c4 * 4 + 1] = v.y;
            Ws[o][c4 * 4 + 2] = v.z; Ws[o][c4 * 4 + 3] = v.w;
        }
        __syncthreads();
#pragma unroll
        for (int kk = 0; kk < 32; kk++) {
            float hreg[4], wreg[8];
#pragma unroll
            for (int r = 0; r < 4; r++) hreg[r] = Hs[ty * 4 + r][kk];
#pragma unroll
            for (int o = 0; o < 8; o++) wreg[o] = Ws[tx * 8 + o][kk];
#pragma unroll
            for (int r = 0; r < 4; r++)
#pragma unroll
                for (int o = 0; o < 8; o++)
                    acc[r][o] = fmaf(hreg[r], wreg[o], acc[r][o]);
        }
        __syncthreads();
    }

    float b[8];
#pragma unroll
    for (int o = 0; o < 8; o++) b[o] = bias[tx * 8 + o];
    float4* out4 = (float4*)out;
#pragma unroll
    for (int r = 0; r < 4; r++) {
        int gr = row0 + ty * 4 + r;
        if (gr < NN) {
            float4 lo = make_float4(acc[r][0] + b[0], acc[r][1] + b[1],
                                    acc[r][2] + b[2], acc[r][3] + b[3]);
            float4 hi = make_float4(acc[r][4] + b[4], acc[r][5] + b[5],
                                    acc[r][6] + b[6], acc[r][7] + b[7]);
            out4[gr * 32 + tx * 2 + 0] = lo;
            out4[gr * 32 + tx * 2 + 1] = hi;
        }
    }
}

extern "C" void kernel_launch(void* const* d_in, const int* in_sizes, int n_in,
                              void* d_out, int out_size) {
    const float* x0   = (const float*)d_in[0];
    const int*   ei   = (const int*)d_in[1];
    const float* Wt   = (const float*)d_in[2];
    const float* bias = (const float*)d_in[3];
    float*       out  = (float*)d_out;
    const int* src = ei;
    const int* dst = ei + EE;

    k_zero_deg<<<(NN + 255) / 256, 256>>>();
    k_degree<<<(EE + 255) / 256, 256>>>(dst);
    k_dinv<<<(NN + 255) / 256, 256>>>();
    k_scan1<<<NBLK, 1024>>>();
    k_scan2<<<1, 32>>>();
    k_scan3<<<NBLK, 1024>>>();
    k_fill<<<(EE + 255) / 256, 256>>>(src, dst);
    k_sort_w<<<(NN + 127) / 128, 128>>>();
    k_init<<<(NN * 32 + 255) / 256, 256>>>((const float4*)x0);

    for (int k = 1; k <= KHOPS; k++)
        k_hop<<<(NN * 32 + 255) / 256, 256>>>(k);

    k_finalize<<<(NN * 32 + 255) / 256, 256>>>((const float4*)x0);
    k_gemm<<<(NN + 63) / 64, 256>>>(Wt, bias, out);
}

// round 10
// speedup vs baseline: 1.4841x; 1.1492x over previous
#include <cuda_runtime.h>
#include <cuda_fp16.h>

#define NN 50000
#define EE 1600000
#define KHOPS 16
#define NBLK ((NN + 1023) / 1024)
#define PADCAP (EE + 3 * NN + 8)
#define HOPBLOCKS 888   // 148 SMs * 6 blocks -> single wave guaranteed

// ---- device scratch (no allocations allowed) ----
__device__ int      g_deg[NN];
__device__ int      g_rowptr[NN + 1];
__device__ int      g_cursor[NN];
__device__ unsigned short g_col16[PADCAP];
__device__ float    g_dinv[NN];     // (deg+1)^-1/2
__device__ float    g_dinv2[NN];    // (deg+1)^-1
__device__ float    g_rdinv[NN];    // (deg+1)^+1/2
__device__ int      g_bsum[NBLK];
__device__ int      g_ctr[KHOPS + 1];
__device__ __half   g_x[KHOPS + 1][(NN + 1) * 128];  // y-states, fp16; row NN = zeros

__global__ void k_zero_deg() {
    int i = blockIdx.x * blockDim.x + threadIdx.x;
    if (i < NN) g_deg[i] = 0;
}

__global__ void k_degree(const int* __restrict__ dst) {
    int e = blockIdx.x * blockDim.x + threadIdx.x;
    if (e < EE) atomicAdd(&g_deg[dst[e]], 1);
}

__global__ void k_dinv() {
    int i = blockIdx.x * blockDim.x + threadIdx.x;
    if (i < NN) {
        float d = (float)(g_deg[i] + 1);
        float r = rsqrtf(d);
        g_dinv[i]  = r;
        g_dinv2[i] = r * r;
        g_rdinv[i] = sqrtf(d);
    }
}

// ---- 3-phase parallel exclusive scan of padded degrees -> g_rowptr ----
__global__ void k_scan1() {
    __shared__ int tmp[1024];
    int t = threadIdx.x;
    int i = blockIdx.x * 1024 + t;
    int v = (i < NN) ? ((g_deg[i] + 3) & ~3) : 0;   // pad rows to multiple of 4
    tmp[t] = v;
    __syncthreads();
#pragma unroll
    for (int off = 1; off < 1024; off <<= 1) {
        int add = (t >= off) ? tmp[t - off] : 0;
        __syncthreads();
        tmp[t] += add;
        __syncthreads();
    }
    if (i < NN) g_rowptr[i] = tmp[t] - v;
    if (t == 1023) g_bsum[blockIdx.x] = tmp[t];
}

__global__ void k_scan2() {
    if (threadIdx.x == 0) {
        int acc = 0;
        for (int b = 0; b < NBLK; b++) { int v = g_bsum[b]; g_bsum[b] = acc; acc += v; }
        g_rowptr[NN] = acc;
    }
}

__global__ void k_scan3() {
    int i = blockIdx.x * 1024 + threadIdx.x;
    if (i < NN) {
        int r = g_rowptr[i] + g_bsum[blockIdx.x];
        g_rowptr[i] = r;
        g_cursor[i] = r;
    }
}

__global__ void k_fill(const int* __restrict__ src, const int* __restrict__ dst) {
    int e = blockIdx.x * blockDim.x + threadIdx.x;
    if (e < EE) {
        int d = dst[e];
        int p = atomicAdd(&g_cursor[d], 1);
        g_col16[p] = (unsigned short)src[e];
    }
}

// deterministic order: warp-per-row SMEM rank sort by src id; fill padding with NN
__global__ void __launch_bounds__(256) k_sort() {
    __shared__ unsigned short buf[8][160];
    int warp = threadIdx.x >> 5, lane = threadIdx.x & 31;
    int r = blockIdx.x * 8 + warp;
    if (r >= NN) return;
    int beg  = g_rowptr[r];
    int deg  = g_deg[r];
    int plen = g_rowptr[r + 1] - beg;
    if (deg <= 160) {
        for (int i = lane; i < deg; i += 32) buf[warp][i] = g_col16[beg + i];
        __syncwarp();
        for (int i = lane; i < deg; i += 32) {
            int v = buf[warp][i];
            int rank = 0;
            for (int j = 0; j < deg; j++) {
                int u = buf[warp][j];
                rank += (u < v) || (u == v && j < i);
            }
            g_col16[beg + rank] = (unsigned short)v;
        }
    } else if (lane == 0) {          // practically unreachable fallback
        for (int i = beg + 1; i < beg + deg; i++) {
            unsigned short key = g_col16[i];
            int j = i - 1;
            while (j >= beg && g_col16[j] > key) { g_col16[j + 1] = g_col16[j]; j--; }
            g_col16[j + 1] = key;
        }
    }
    for (int i = deg + lane; i < plen; i += 32) g_col16[beg + i] = (unsigned short)NN;
}

// y0 = dinv * x0 -> fp16; zero row NN of all buffers; zero hop counters
__global__ void k_init(const float4* __restrict__ x0) {
    int i = blockIdx.x * blockDim.x + threadIdx.x;
    if (i < NN * 32) {
        int row = i >> 5;
        float d = g_dinv[row];
        float4 v = x0[i];
        uint2 u;
        __half2 lo = __floats2half2_rn(d * v.x, d * v.y);
        __half2 hi = __floats2half2_rn(d * v.z, d * v.w);
        u.x = *reinterpret_cast<unsigned*>(&lo);
        u.y = *reinterpret_cast<unsigned*>(&hi);
        ((uint2*)g_x[0])[i] = u;
    }
    if (i < (KHOPS + 1) * 32)
        ((uint2*)g_x[i >> 5])[NN * 32 + (i & 31)] = make_uint2(0u, 0u);
    if (i < KHOPS + 1) g_ctr[i] = 0;
}

__device__ __forceinline__ void acc4(float& ax, float& ay, float& az, float& aw, uint2 u) {
    __half2 h0 = *reinterpret_cast<__half2*>(&u.x);
    __half2 h1 = *reinterpret_cast<__half2*>(&u.y);
    float2 f0 = __half22float2(h0);
    float2 f1 = __half22float2(h1);
    ax += f0.x; ay += f0.y; az += f1.x; aw += f1.y;
}

// work-stealing hop: warps grab 2-node batches; one warp per node,
// lane = one uint2 (4 fp16 cols) of the 256B row
__global__ void __launch_bounds__(256, 6) k_hop(int k) {
    const __half* __restrict__ xin = g_x[k - 1];
    __half* __restrict__ xout = g_x[k];
    int lane = threadIdx.x & 31;
    for (;;) {
        int base = 0;
        if (lane == 0) base = atomicAdd(&g_ctr[k], 2);
        base = __shfl_sync(0xffffffffu, base, 0);
        if (base >= NN) break;
        int nend = (base + 2 < NN) ? base + 2 : NN;
        for (int n = base; n < nend; n++) {
            float s2 = g_dinv2[n];
            float ax = 0.f, ay = 0.f, az = 0.f, aw = 0.f;
            acc4(ax, ay, az, aw, ((const uint2*)(xin + (size_t)n * 128))[lane]);  // self
            int j   = g_rowptr[n];
            int end = g_rowptr[n + 1];
            for (; j < end; j += 4) {
                uint2 cc = *(const uint2*)(g_col16 + j);   // 4 ids, 8B aligned
                int c0 = cc.x & 0xFFFF, c1 = cc.x >> 16;
                int c2 = cc.y & 0xFFFF, c3 = cc.y >> 16;
                uint2 v0 = ((const uint2*)(xin + (size_t)c0 * 128))[lane];
                uint2 v1 = ((const uint2*)(xin + (size_t)c1 * 128))[lane];
                uint2 v2 = ((const uint2*)(xin + (size_t)c2 * 128))[lane];
                uint2 v3 = ((const uint2*)(xin + (size_t)c3 * 128))[lane];
                acc4(ax, ay, az, aw, v0);
                acc4(ax, ay, az, aw, v1);
                acc4(ax, ay, az, aw, v2);
                acc4(ax, ay, az, aw, v3);
            }
            uint2 o;
            __half2 lo = __floats2half2_rn(s2 * ax, s2 * ay);
            __half2 hi = __floats2half2_rn(s2 * az, s2 * aw);
            o.x = *reinterpret_cast<unsigned*>(&lo);
            o.y = *reinterpret_cast<unsigned*>(&hi);
            ((uint2*)(xout + (size_t)n * 128))[lane] = o;
        }
    }
}

// Fused finalize + GEMM. h[m,:] = 0.05*x0 + (0.95/16)*rdinv*sum_k y_k, built in SMEM,
// then C[m,o] = sum_d h[m,d]*W[o,d] + bias[o]. 64-row tile.
__global__ void __launch_bounds__(256) k_gemm(const float4* __restrict__ x0,
                                              const float* __restrict__ Wt,
                                              const float* __restrict__ bias,
                                              float* __restrict__ out) {
    __shared__ float Hs[64][129];
    __shared__ float Ws[128][34];
    int tid = threadIdx.x;
    int row0 = blockIdx.x * 64;
    const float cf = 0.95f / 16.0f;

    // build h tile: 2048 uint2-chunks (64 rows x 32 chunks), 8 per thread
#pragma unroll
    for (int q = 0; q < 8; q++) {
        int p = tid + 256 * q;          // 0..2047
        int r = p >> 5, c4 = p & 31;
        int gr = row0 + r;
        float hx = 0.f, hy = 0.f, hz = 0.f, hw = 0.f;
        if (gr < NN) {
            float sx = 0.f, sy = 0.f, sz = 0.f, sw = 0.f;
#pragma unroll
            for (int k = 1; k <= KHOPS; k++) {
                uint2 u = ((const uint2*)(g_x[k] + (size_t)gr * 128))[c4];
                acc4(sx, sy, sz, sw, u);
            }
            float rd = g_rdinv[gr];
            float4 v = x0[gr * 32 + c4];
            hx = fmaf(cf * rd, sx, 0.05f * v.x);
            hy = fmaf(cf * rd, sy, 0.05f * v.y);
            hz = fmaf(cf * rd, sz, 0.05f * v.z);
            hw = fmaf(cf * rd, sw, 0.05f * v.w);
        }
        Hs[r][c4 * 4 + 0] = hx; Hs[r][c4 * 4 + 1] = hy;
        Hs[r][c4 * 4 + 2] = hz; Hs[r][c4 * 4 + 3] = hw;
    }

    int tx = tid & 15;    // out cols tx*8..+7
    int ty = tid >> 4;    // rows ty*4..+3
    float acc[4][8];
#pragma unroll
    for (int r = 0; r < 4; r++)
#pragma unroll
        for (int o = 0; o < 8; o++) acc[r][o] = 0.f;

    const float4* w4 = (const float4*)Wt;
    __syncthreads();
    for (int kc = 0; kc < 4; kc++) {
#pragma unroll
        for (int q = 0; q < 4; q++) {
            int idx = tid * 4 + q;       // 0..1023
            int o = idx >> 3, c4 = idx & 7;
            float4 v = w4[o * 32 + kc * 8 + c4];
            Ws[o][c4 * 4 + 0] = v.x; Ws[o][c4 * 4 + 1] = v.y;
            Ws[o][c4 * 4 + 2] = v.z; Ws[o][c4 * 4 + 3] = v.w;
        }
        __syncthreads();
#pragma unroll
        for (int kk = 0; kk < 32; kk++) {
            int kg = kc * 32 + kk;
            float hreg[4], wreg[8];
#pragma unroll
            for (int r = 0; r < 4; r++) hreg[r] = Hs[ty * 4 + r][kg];
#pragma unroll
            for (int o = 0; o < 8; o++) wreg[o] = Ws[tx * 8 + o][kk];
#pragma unroll
            for (int r = 0; r < 4; r++)
#pragma unroll
                for (int o = 0; o < 8; o++)
                    acc[r][o] = fmaf(hreg[r], wreg[o], acc[r][o]);
        }
        __syncthreads();
    }

    float b[8];
#pragma unroll
    for (int o = 0; o < 8; o++) b[o] = bias[tx * 8 + o];
    float4* out4 = (float4*)out;
#pragma unroll
    for (int r = 0; r < 4; r++) {
        int gr = row0 + ty * 4 + r;
        if (gr < NN) {
            float4 lo = make_float4(acc[r][0] + b[0], acc[r][1] + b[1],
                                    acc[r][2] + b[2], acc[r][3] + b[3]);
            float4 hi = make_float4(acc[r][4] + b[4], acc[r][5] + b[5],
                                    acc[r][6] + b[6], acc[r][7] + b[7]);
            out4[gr * 32 + tx * 2 + 0] = lo;
            out4[gr * 32 + tx * 2 + 1] = hi;
        }
    }
}

extern "C" void kernel_launch(void* const* d_in, const int* in_sizes, int n_in,
                              void* d_out, int out_size) {
    const float* x0   = (const float*)d_in[0];
    const int*   ei   = (const int*)d_in[1];
    const float* Wt   = (const float*)d_in[2];
    const float* bias = (const float*)d_in[3];
    float*       out  = (float*)d_out;
    const int* src = ei;
    const int* dst = ei + EE;

    k_zero_deg<<<(NN + 255) / 256, 256>>>();
    k_degree<<<(EE + 255) / 256, 256>>>(dst);
    k_dinv<<<(NN + 255) / 256, 256>>>();
    k_scan1<<<NBLK, 1024>>>();
    k_scan2<<<1, 32>>>();
    k_scan3<<<NBLK, 1024>>>();
    k_fill<<<(EE + 255) / 256, 256>>>(src, dst);
    k_sort<<<(NN + 7) / 8, 256>>>();
    k_init<<<(NN * 32 + 255) / 256, 256>>>((const float4*)x0);

    for (int k = 1; k <= KHOPS; k++)
        k_hop<<<HOPBLOCKS, 256>>>(k);

    k_gemm<<<(NN + 63) / 64, 256>>>((const float4*)x0, Wt, bias, out);
}

// round 12
// speedup vs baseline: 1.5432x; 1.0398x over previous
#include <cuda_runtime.h>
#include <cuda_fp16.h>

#define NN 50000
#define EE 1600000
#define KHOPS 16
#define NBLK ((NN + 1023) / 1024)
#define PADCAP (EE + 3 * NN + 8)
#define HOPBLOCKS 740   // 148 SMs * 5 resident blocks -> single wave

// ---- device scratch (no allocations allowed) ----
__device__ int      g_deg[NN];
__device__ int      g_rowptr[NN + 1];
__device__ int      g_cursor[NN];
__device__ unsigned short g_col16[PADCAP];
__device__ float    g_dinv2[NN];    // (deg+1)^-1
__device__ float    g_rdinv[NN];    // (deg+1)^+1/2
__device__ float    g_dinv[NN];     // (deg+1)^-1/2
__device__ int      g_bsum[NBLK];
__device__ int      g_ctr[KHOPS + 1];
__device__ __half   g_x[KHOPS + 1][(NN + 1) * 128];  // y-states, fp16; row NN = zeros

__global__ void k_zero_deg() {
    int i = blockIdx.x * blockDim.x + threadIdx.x;
    if (i < NN) g_deg[i] = 0;
}

__global__ void k_degree(const int* __restrict__ dst) {
    int e = blockIdx.x * blockDim.x + threadIdx.x;
    if (e < EE) atomicAdd(&g_deg[dst[e]], 1);
}

// ---- scan phase 1 (+ fused dinv computation) ----
__global__ void k_scan1() {
    __shared__ int tmp[1024];
    int t = threadIdx.x;
    int i = blockIdx.x * 1024 + t;
    int dg = (i < NN) ? g_deg[i] : 0;
    if (i < NN) {
        float d = (float)(dg + 1);
        float r = rsqrtf(d);
        g_dinv[i]  = r;
        g_dinv2[i] = r * r;
        g_rdinv[i] = sqrtf(d);
    }
    int v = (dg + 3) & ~3;                    // pad rows to multiple of 4
    tmp[t] = v;
    __syncthreads();
#pragma unroll
    for (int off = 1; off < 1024; off <<= 1) {
        int add = (t >= off) ? tmp[t - off] : 0;
        __syncthreads();
        tmp[t] += add;
        __syncthreads();
    }
    if (i < NN) g_rowptr[i] = tmp[t] - v;
    if (t == 1023) g_bsum[blockIdx.x] = tmp[t];
}

__global__ void k_scan2() {
    if (threadIdx.x == 0) {
        int acc = 0;
        for (int b = 0; b < NBLK; b++) { int v = g_bsum[b]; g_bsum[b] = acc; acc += v; }
        g_rowptr[NN] = acc;
    }
}

__global__ void k_scan3() {
    int i = blockIdx.x * 1024 + threadIdx.x;
    if (i < NN) {
        int r = g_rowptr[i] + g_bsum[blockIdx.x];
        g_rowptr[i] = r;
        g_cursor[i] = r;
    }
}

__global__ void k_fill(const int* __restrict__ src, const int* __restrict__ dst) {
    int e = blockIdx.x * blockDim.x + threadIdx.x;
    if (e < EE) {
        int d = dst[e];
        int p = atomicAdd(&g_cursor[d], 1);
        g_col16[p] = (unsigned short)src[e];
    }
}

// deterministic order: warp-per-row SMEM rank sort by src id; fill padding with NN
__global__ void __launch_bounds__(256) k_sort() {
    __shared__ unsigned short buf[8][160];
    int warp = threadIdx.x >> 5, lane = threadIdx.x & 31;
    int r = blockIdx.x * 8 + warp;
    if (r >= NN) return;
    int beg  = g_rowptr[r];
    int deg  = g_deg[r];
    int plen = g_rowptr[r + 1] - beg;
    if (deg <= 160) {
        for (int i = lane; i < deg; i += 32) buf[warp][i] = g_col16[beg + i];
        __syncwarp();
        for (int i = lane; i < deg; i += 32) {
            int v = buf[warp][i];
            int rank = 0;
            for (int j = 0; j < deg; j++) {
                int u = buf[warp][j];
                rank += (u < v) || (u == v && j < i);
            }
            g_col16[beg + rank] = (unsigned short)v;
        }
    } else if (lane == 0) {          // practically unreachable fallback
        for (int i = beg + 1; i < beg + deg; i++) {
            unsigned short key = g_col16[i];
            int j = i - 1;
            while (j >= beg && g_col16[j] > key) { g_col16[j + 1] = g_col16[j]; j--; }
            g_col16[j + 1] = key;
        }
    }
    for (int i = deg + lane; i < plen; i += 32) g_col16[beg + i] = (unsigned short)NN;
}

// y0 = dinv * x0 -> fp16; zero row NN of all buffers; zero hop counters
__global__ void k_init(const float4* __restrict__ x0) {
    int i = blockIdx.x * blockDim.x + threadIdx.x;
    if (i < NN * 32) {
        int row = i >> 5;
        float d = g_dinv[row];
        float4 v = x0[i];
        uint2 u;
        __half2 lo = __floats2half2_rn(d * v.x, d * v.y);
        __half2 hi = __floats2half2_rn(d * v.z, d * v.w);
        u.x = *reinterpret_cast<unsigned*>(&lo);
        u.y = *reinterpret_cast<unsigned*>(&hi);
        ((uint2*)g_x[0])[i] = u;
    }
    if (i < (KHOPS + 1) * 32)
        ((uint2*)g_x[i >> 5])[NN * 32 + (i & 31)] = make_uint2(0u, 0u);
    if (i < KHOPS + 1) g_ctr[i] = 0;
}

__device__ __forceinline__ void acc2(float& ax, float& ay, float& az, float& aw, uint2 u) {
    __half2 h0 = *reinterpret_cast<__half2*>(&u.x);
    __half2 h1 = *reinterpret_cast<__half2*>(&u.y);
    float2 f0 = __half22float2(h0);
    float2 f1 = __half22float2(h1);
    ax += f0.x; ay += f0.y; az += f1.x; aw += f1.y;
}

__device__ __forceinline__ void acc8(float* a, uint4 u) {
    acc2(a[0], a[1], a[2], a[3], make_uint2(u.x, u.y));
    acc2(a[4], a[5], a[6], a[7], make_uint2(u.z, u.w));
}

// work-stealing hop. Warp processes one node; split-warp gather:
// lanes 0-15 handle EVEN neighbors, lanes 16-31 handle ODD neighbors.
// Each lane loads one uint4 (16 B = 8 fp16 cols) of the 256B row -> LDG.128.
// Halves combined at the end via shfl_xor(16). Deterministic order.
__global__ void __launch_bounds__(256, 5) k_hop(int k) {
    const __half* __restrict__ xin = g_x[k - 1];
    __half* __restrict__ xout = g_x[k];
    int lane = threadIdx.x & 31;
    int hi   = lane >> 4;        // 0 = even neighbors, 1 = odd neighbors
    int c16  = lane & 15;        // 16-byte chunk of the row
    for (;;) {
        int base = 0;
        if (lane == 0) base = atomicAdd(&g_ctr[k], 2);
        base = __shfl_sync(0xffffffffu, base, 0);
        if (base >= NN) break;
        int nend = (base + 2 < NN) ? base + 2 : NN;
        for (int n = base; n < nend; n++) {
            float a[8];
#pragma unroll
            for (int q = 0; q < 8; q++) a[q] = 0.f;
            // self term: lo half reads self row, hi half reads zero row
            {
                int sid = hi ? NN : n;
                uint4 v = ((const uint4*)(xin + (size_t)sid * 128))[c16];
                acc8(a, v);
            }
            int j   = g_rowptr[n];
            int end = g_rowptr[n + 1];
            for (; j < end; j += 4) {            // 4 neighbors = 2 pairs / iter
                uint2 cc = *(const uint2*)(g_col16 + j);
                int cA = hi ? (int)(cc.x >> 16) : (int)(cc.x & 0xFFFF);
                int cB = hi ? (int)(cc.y >> 16) : (int)(cc.y & 0xFFFF);
                uint4 vA = ((const uint4*)(xin + (size_t)cA * 128))[c16];
                uint4 vB = ((const uint4*)(xin + (size_t)cB * 128))[c16];
                acc8(a, vA);
                acc8(a, vB);
            }
            // combine even/odd halves (fixed order -> deterministic)
#pragma unroll
            for (int q = 0; q < 8; q++)
                a[q] += __shfl_xor_sync(0xffffffffu, a[q], 16);
            if (hi == 0) {
                float s2 = g_dinv2[n];
                uint4 o;
                __half2 p0 = __floats2half2_rn(s2 * a[0], s2 * a[1]);
                __half2 p1 = __floats2half2_rn(s2 * a[2], s2 * a[3]);
                __half2 p2 = __floats2half2_rn(s2 * a[4], s2 * a[5]);
                __half2 p3 = __floats2half2_rn(s2 * a[6], s2 * a[7]);
                o.x = *reinterpret_cast<unsigned*>(&p0);
                o.y = *reinterpret_cast<unsigned*>(&p1);
                o.z = *reinterpret_cast<unsigned*>(&p2);
                o.w = *reinterpret_cast<unsigned*>(&p3);
                ((uint4*)(xout + (size_t)n * 128))[c16] = o;
            }
        }
    }
}

// Fused finalize + GEMM. h[m,:] = 0.05*x0 + (0.95/16)*rdinv*sum_k y_k, built in SMEM,
// then C[m,o] = sum_d h[m,d]*W[o,d] + bias[o]. 64-row tile.
__global__ void __launch_bounds__(256) k_gemm(const float4* __restrict__ x0,
                                              const float* __restrict__ Wt,
                                              const float* __restrict__ bias,
                                              float* __restrict__ out) {
    __shared__ float Hs[64][129];
    __shared__ float Ws[128][34];
    int tid = threadIdx.x;
    int row0 = blockIdx.x * 64;
    const float cf = 0.95f / 16.0f;

    // build h tile: 2048 uint2-chunks (64 rows x 32 chunks), 8 per thread
#pragma unroll
    for (int q = 0; q < 8; q++) {
        int p = tid + 256 * q;          // 0..2047
        int r = p >> 5, c4 = p & 31;
        int gr = row0 + r;
        float hx = 0.f, hy = 0.f, hz = 0.f, hw = 0.f;
        if (gr < NN) {
            float sx = 0.f, sy = 0.f, sz = 0.f, sw = 0.f;
#pragma unroll
            for (int k = 1; k <= KHOPS; k++) {
                uint2 u = ((const uint2*)(g_x[k] + (size_t)gr * 128))[c4];
                acc2(sx, sy, sz, sw, u);
            }
            float rd = g_rdinv[gr];
            float4 v = x0[gr * 32 + c4];
            hx = fmaf(cf * rd, sx, 0.05f * v.x);
            hy = fmaf(cf * rd, sy, 0.05f * v.y);
            hz = fmaf(cf * rd, sz, 0.05f * v.z);
            hw = fmaf(cf * rd, sw, 0.05f * v.w);
        }
        Hs[r][c4 * 4 + 0] = hx; Hs[r][c4 * 4 + 1] = hy;
        Hs[r][c4 * 4 + 2] = hz; Hs[r][c4 * 4 + 3] = hw;
    }

    int tx = tid & 15;    // out cols tx*8..+7
    int ty = tid >> 4;    // rows ty*4..+3
    float acc[4][8];
#pragma unroll
    for (int r = 0; r < 4; r++)
#pragma unroll
        for (int o = 0; o < 8; o++) acc[r][o] = 0.f;

    const float4* w4 = (const float4*)Wt;
    __syncthreads();
    for (int kc = 0; kc < 4; kc++) {
#pragma unroll
        for (int q = 0; q < 4; q++) {
            int idx = tid * 4 + q;       // 0..1023
            int o = idx >> 3, c4 = idx & 7;
            float4 v = w4[o * 32 + kc * 8 + c4];
            Ws[o][c4 * 4 + 0] = v.x; Ws[o][c4 * 4 + 1] = v.y;
            Ws[o][c4 * 4 + 2] = v.z; Ws[o][c4 * 4 + 3] = v.w;
        }
        __syncthreads();
#pragma unroll
        for (int kk = 0; kk < 32; kk++) {
            int kg = kc * 32 + kk;
            float hreg[4], wreg[8];
#pragma unroll
            for (int r = 0; r < 4; r++) hreg[r] = Hs[ty * 4 + r][kg];
#pragma unroll
            for (int o = 0; o < 8; o++) wreg[o] = Ws[tx * 8 + o][kk];
#pragma unroll
            for (int r = 0; r < 4; r++)
#pragma unroll
                for (int o = 0; o < 8; o++)
                    acc[r][o] = fmaf(hreg[r], wreg[o], acc[r][o]);
        }
        __syncthreads();
    }

    float b[8];
#pragma unroll
    for (int o = 0; o < 8; o++) b[o] = bias[tx * 8 + o];
    float4* out4 = (float4*)out;
#pragma unroll
    for (int r = 0; r < 4; r++) {
        int gr = row0 + ty * 4 + r;
        if (gr < NN) {
            float4 lo = make_float4(acc[r][0] + b[0], acc[r][1] + b[1],
                                    acc[r][2] + b[2], acc[r][3] + b[3]);
            float4 hi4 = make_float4(acc[r][4] + b[4], acc[r][5] + b[5],
                                     acc[r][6] + b[6], acc[r][7] + b[7]);
            out4[gr * 32 + tx * 2 + 0] = lo;
            out4[gr * 32 + tx * 2 + 1] = hi4;
        }
    }
}

extern "C" void kernel_launch(void* const* d_in, const int* in_sizes, int n_in,
                              void* d_out, int out_size) {
    const float* x0   = (const float*)d_in[0];
    const int*   ei   = (const int*)d_in[1];
    const float* Wt   = (const float*)d_in[2];
    const float* bias = (const float*)d_in[3];
    float*       out  = (float*)d_out;
    const int* src = ei;
    const int* dst = ei + EE;

    k_zero_deg<<<(NN + 255) / 256, 256>>>();
    k_degree<<<(EE + 255) / 256, 256>>>(dst);
    k_scan1<<<NBLK, 1024>>>();
    k_scan2<<<1, 32>>>();
    k_scan3<<<NBLK, 1024>>>();
    k_fill<<<(EE + 255) / 256, 256>>>(src, dst);
    k_sort<<<(NN + 7) / 8, 256>>>();
    k_init<<<(NN * 32 + 255) / 256, 256>>>((const float4*)x0);

    for (int k = 1; k <= KHOPS; k++)
        k_hop<<<HOPBLOCKS, 256>>>(k);

    k_gemm<<<(NN + 63) / 64, 256>>>((const float4*)x0, Wt, bias, out);
}